// round 3
// baseline (speedup 1.0000x reference)
#include <cuda_runtime.h>

#define Dd     64
#define WROW   132            // padded SMEM row stride (floats): 528B, 16B-aligned, bank-spread
#define HALF   512
#define NB     4              // batches per CTA
#define NT     256
#define SM_WF  (3 * Dd * WROW)        // W triple buffer, floats
#define SM_VF  (2 * NB * 68)          // v ping-pong, floats
#define SMEM_BYTES ((SM_WF + SM_VF) * 4)

__device__ float g_vL[64 * Dd];
__device__ float g_wR[64 * Dd];

__device__ __forceinline__ unsigned su(const void* p) {
    return (unsigned)__cvta_generic_to_shared(p);
}
__device__ __forceinline__ void cp16(unsigned d, const float* s) {
    asm volatile("cp.async.cg.shared.global [%0], [%1], 16;" :: "r"(d), "l"(s) : "memory");
}
__device__ __forceinline__ unsigned long long pk2(float a, float b) {
    unsigned long long r;
    asm("mov.b64 %0, {%1,%2};" : "=l"(r) : "f"(a), "f"(b));
    return r;
}
__device__ __forceinline__ unsigned long long fma2(unsigned long long a,
                                                   unsigned long long b,
                                                   unsigned long long c) {
    unsigned long long d;
    asm("fma.rn.f32x2 %0, %1, %2, %3;" : "=l"(d) : "l"(a), "l"(b), "l"(c));
    return d;
}
__device__ __forceinline__ float2 up2(unsigned long long v) {
    float2 f;
    asm("mov.b64 {%0,%1}, %2;" : "=f"(f.x), "=f"(f.y) : "l"(v));
    return f;
}

// Stage one 64x128-float W site (32KB) into padded SMEM rows (8 chunks/thread).
__device__ __forceinline__ void stageW(float* dst, const float* src, int t) {
#pragma unroll
    for (int k = 0; k < 8; k++) {
        int c   = t + k * NT;          // 0..2047 16B chunks
        int row = c >> 5;              // 32 chunks per 128-float row
        int col = (c & 31) << 2;       // float offset in row
        cp16(su(dst + row * WROW + col), src + row * 128 + col);
    }
}

__global__ void __launch_bounds__(NT, 1)
chain_kernel(const float* __restrict__ x, const float* __restrict__ Wl,
             const float* __restrict__ Wr)
{
    extern __shared__ float sm[];
    float* Wb3  = sm;                  // [3][64*WROW]
    float* vbuf = sm + SM_WF;          // [2][NB][68]

    const int t    = threadIdx.x;
    const int side = blockIdx.x >> 4;            // 0 = left chain, 1 = right chain
    const int gb   = (blockIdx.x & 15) * NB;     // first batch of this CTA
    const int bl   = t & 3;                      // local batch
    const int q    = t >> 2;                     // 0..63 output lane
    const float* W = side ? Wr : Wl;

    // init v ping buffer 0 to e0
    for (int i = t; i < NB * 68; i += NT) vbuf[i] = 0.f;
    __syncthreads();
    if (t < NB) vbuf[t * 68] = 1.f;

    // prologue: stage first two sites
    {
        int s0 = side ? (HALF - 1) : 0;
        int s1 = side ? (HALF - 2) : 1;
        stageW(Wb3,              W + s0 * 8192, t);
        asm volatile("cp.async.commit_group;" ::: "memory");
        stageW(Wb3 + Dd * WROW,  W + s1 * 8192, t);
        asm volatile("cp.async.commit_group;" ::: "memory");
    }

    const float* xb = x + (gb + bl) * 2048;
    float last = 0.f;

    for (int i = 0; i < HALF; ++i) {
        const int sl    = side ? (HALF - 1 - i) : i;    // local site
        const int gsite = side ? (HALF + sl)    : sl;   // global site for x
        const float* Wb = Wb3 + (i % 3) * (Dd * WROW);

        if (i < HALF - 1) asm volatile("cp.async.wait_group 1;" ::: "memory");
        else              asm volatile("cp.async.wait_group 0;" ::: "memory");
        __syncthreads();

        const float* vin  = vbuf + (i & 1) * (NB * 68) + bl * 68;
        float*       vout = vbuf + ((i & 1) ^ 1) * (NB * 68);
        const float2 xv   = *(const float2*)(xb + gsite * 2);

        unsigned long long a0 = 0ull, a1 = 0ull;
        if (side == 0) {
            // v_new[q] = x0*sum_l v[l]*W0[l,q] + x1*sum_l v[l]*W1[l,q]
#pragma unroll
            for (int l = 0; l < Dd; l += 2) {
                float2 vl = *(const float2*)(vin + l);
                unsigned long long w0 = *(const unsigned long long*)(Wb + l * WROW + 2 * q);
                unsigned long long w1 = *(const unsigned long long*)(Wb + (l + 1) * WROW + 2 * q);
                a0 = fma2(pk2(vl.x, vl.x), w0, a0);
                a1 = fma2(pk2(vl.y, vl.y), w1, a1);
            }
        } else {
            // w_new[q] = x0*sum_r W0[q,r]*w[r] + x1*sum_r W1[q,r]*w[r]
            const float* Wrow = Wb + q * WROW;
#pragma unroll
            for (int j = 0; j < 32; j++) {
                float2 wr = *(const float2*)(vin + 2 * j);
                ulonglong2 ww = *(const ulonglong2*)(Wrow + 4 * j);
                a0 = fma2(pk2(wr.x, wr.x), ww.x, a0);
                a1 = fma2(pk2(wr.y, wr.y), ww.y, a1);
            }
        }
        float2 A0 = up2(a0), A1 = up2(a1);
        last = xv.x * (A0.x + A1.x) + xv.y * (A0.y + A1.y);
        vout[bl * 68 + q] = last;

        if (i + 2 < HALF) {
            int sn = side ? (HALF - 1 - (i + 2)) : (i + 2);
            stageW(Wb3 + ((i + 2) % 3) * (Dd * WROW), W + sn * 8192, t);
            asm volatile("cp.async.commit_group;" ::: "memory");
        }
    }

    if (side == 0) g_vL[(gb + bl) * Dd + q] = last;
    else           g_wR[(gb + bl) * Dd + q] = last;
}

// out[b,o] = sum_{l,r} vL[b,l] * core[o,l,r] * wR[b,r]; one block per (b,o)
__global__ void __launch_bounds__(64, 16)
combine_kernel(const float* __restrict__ core, float* __restrict__ out)
{
    const int b = blockIdx.x / 10;
    const int o = blockIdx.x % 10;
    const int l = threadIdx.x;

    __shared__ float wsh[Dd];
    __shared__ float red[2];
    wsh[l] = g_wR[b * Dd + l];
    __syncthreads();

    const float* crow = core + o * (Dd * Dd) + l * Dd;
    float s = 0.f;
#pragma unroll 8
    for (int r = 0; r < Dd; r++) s = fmaf(crow[r], wsh[r], s);
    float p = g_vL[b * Dd + l] * s;

#pragma unroll
    for (int off = 16; off; off >>= 1)
        p += __shfl_down_sync(0xffffffffu, p, off);
    if ((l & 31) == 0) red[l >> 5] = p;
    __syncthreads();
    if (l == 0) out[b * 10 + o] = red[0] + red[1];
}

extern "C" void kernel_launch(void* const* d_in, const int* in_sizes, int n_in,
                              void* d_out, int out_size)
{
    const float* x    = (const float*)d_in[0];
    const float* Wl   = (const float*)d_in[1];
    const float* core = (const float*)d_in[2];
    const float* Wr   = (const float*)d_in[3];
    float* out = (float*)d_out;

    cudaFuncSetAttribute(chain_kernel,
                         cudaFuncAttributeMaxDynamicSharedMemorySize, SMEM_BYTES);

    chain_kernel<<<32, NT, SMEM_BYTES>>>(x, Wl, Wr);
    combine_kernel<<<640, 64>>>(core, out);
}